// round 17
// baseline (speedup 1.0000x reference)
#include <cuda_runtime.h>

// ChunkedValueCrossAttn: softmax over a single context token == 1.0, so
// y[b,c,h,w] = (Wo @ (Wv @ context[b]))[c] + bo[c] — a constant per (b,c)
// broadcast over HxW. x/Wq/Wk are dead inputs; the problem reduces to
// computing 128 scalars and writing 536.9 MB (write-only, HBM-bound).
//
// Plateau after 16 rounds: kernel ~74us / DRAM ~81% / ~7.25 TB/s (~91% of
// spec) for every high-occupancy shape. This round probes the LAST unmapped
// grid cell: 65536 blocks x 2 f4/thread (8KB/block) — finest tail
// granularity with still-adequate per-thread store depth. Prologue is the
// proven best (round 12): barrier-free warp-redundant constant via
// y = bo[c] + (Wo[c,:] @ Wv) . ctx, coalesced loads, one 5-shfl butterfly.

#define B_       2
#define CQ_      64
#define INNER_   32
#define CTX_     16
#define TPB_     256
#define F4_PER_THREAD_ 2
#define F4_PER_BLOCK_  (TPB_ * F4_PER_THREAD_)   // 512 float4 = 8KB
// 2^18 f4 per slab / 512 = 512 blocks per slab

__global__ void __launch_bounds__(TPB_) fused_fill_kernel(
        float4* __restrict__ out,
        const float* __restrict__ context,
        const float* __restrict__ Wv,
        const float* __restrict__ Wo,
        const float* __restrict__ bo) {
    unsigned int slab = blockIdx.x >> 9;       // 512 blocks per slab
    unsigned int b = slab >> 6;                // batch index
    unsigned int c = slab & 63u;               // channel index

    const unsigned FULL = 0xFFFFFFFFu;
    int l = threadIdx.x & 31;

    // ctx quarter for this lane: context[b] is 16 floats = 4 float4.
    float4 ctxq = ((const float4*)context)[b * 4 + (l & 3)];
    float wo_l  = Wo[c * INNER_ + l];          // lane l holds Wo[c,l], coalesced
    float bias  = bo[c];                       // uniform broadcast

    // Wv: 32 rows x 16 floats = 128 float4. Iter t, lane l loads float4
    // idx = 32t+l -> row 8t+(l>>2), quarter l&3. Coalesced 512B per iter.
    const float4* Wv4 = (const float4*)Wv;
    float4 acc4 = make_float4(0.f, 0.f, 0.f, 0.f);
    #pragma unroll
    for (int t = 0; t < 4; ++t) {
        float4 w  = Wv4[t * 32 + l];
        float woc = __shfl_sync(FULL, wo_l, 8 * t + (l >> 2));
        acc4.x += woc * w.x;
        acc4.y += woc * w.y;
        acc4.z += woc * w.z;
        acc4.w += woc * w.w;
    }

    // Per-lane partial covers (rows 8t+(l>>2), quarter l&3) exactly once
    // across the warp -> ONE butterfly finishes the double sum.
    float s = acc4.x * ctxq.x + acc4.y * ctxq.y
            + acc4.z * ctxq.z + acc4.w * ctxq.w;
    #pragma unroll
    for (int off = 16; off > 0; off >>= 1)
        s += __shfl_xor_sync(FULL, s, off);    // full sum in ALL lanes

    float val = s + bias;

    float4 f = make_float4(val, val, val, val);
    unsigned int base = blockIdx.x * (unsigned)F4_PER_BLOCK_ + threadIdx.x;
    #pragma unroll
    for (int k = 0; k < F4_PER_THREAD_; ++k)
        out[base + k * (unsigned)TPB_] = f;
}

extern "C" void kernel_launch(void* const* d_in, const int* in_sizes, int n_in,
                              void* d_out, int out_size) {
    // metadata order: x, context, Wq, Wk, Wv, Wo, bo
    const float* context = (const float*)d_in[1];
    const float* Wv      = (const float*)d_in[4];
    const float* Wo      = (const float*)d_in[5];
    const float* bo      = (const float*)d_in[6];

    // out_size = 134,217,728 floats = 33,554,432 float4 -> 65536 blocks exact
    int n4 = out_size / 4;
    int blocks = n4 / F4_PER_BLOCK_;   // 65536
    fused_fill_kernel<<<blocks, TPB_>>>((float4*)d_out, context, Wv, Wo, bo);
}